// round 15
// baseline (speedup 1.0000x reference)
#include <cuda_runtime.h>
#include <cuda_fp16.h>
#include <cstdint>

// ---------------------------------------------------------------------------
// GAT 3-layer forward, gather-based (CSR by dst).
// R15: (a) measurement round -- node0 launched TWICE (idempotent) so the wall
// delta vs R14 reveals the node kernel's true cost; (b) gemm2 (BN=64) gets
// launch_bounds(512,2) for 2 blocks/SM. Everything else identical to R14.
// ---------------------------------------------------------------------------

#define MAXN 50000
#define MAXE 800000
#define MAXW 128

__device__ __half g_feat_h[MAXN * MAXW];   // gather operand (fp16 feat)
__device__ __half g_ahi[MAXN * MAXW];      // next-layer A, hi plane
__device__ __half g_alo[MAXN * MAXW];      // next-layer A, lo plane
__device__ __half g_w1hi[128 * 128], g_w1lo[128 * 128];
__device__ __half g_w2hi[64 * 128],  g_w2lo[64 * 128];
__device__ float  g_t [MAXN * 2];
__device__ int g_cnt[MAXN + 1];
__device__ int g_ptr[MAXN + 1];
__device__ int g_cur[MAXN + 1];
__device__ int g_csr[MAXE];

__device__ __forceinline__ void mma16816(float* d, const uint32_t* a, const uint32_t* b) {
    asm volatile(
        "mma.sync.aligned.m16n8k16.row.col.f32.f16.f16.f32 "
        "{%0,%1,%2,%3}, {%4,%5,%6,%7}, {%8,%9}, {%0,%1,%2,%3};\n"
        : "+f"(d[0]), "+f"(d[1]), "+f"(d[2]), "+f"(d[3])
        : "r"(a[0]), "r"(a[1]), "r"(a[2]), "r"(a[3]), "r"(b[0]), "r"(b[1]));
}

// ---------------- W hi/lo plane precompute ----------------
__global__ void wconv_kernel(const float* __restrict__ W,
                             __half* __restrict__ whi, __half* __restrict__ wlo,
                             int total) {
    int i = blockIdx.x * blockDim.x + threadIdx.x;
    if (i >= total) return;
    float v = W[i];
    __half h = __float2half(v);
    whi[i] = h;
    wlo[i] = __float2half(v - __half2float(h));
}

// ---------------- tensor-core GEMM + fused score epilogue ----------------
template <int BN, int H, bool CONV, int MINBLK>
__global__ void __launch_bounds__(512, MINBLK)
gemm_tc_kernel(const float* __restrict__ A,
               const __half* __restrict__ Ahi_g, const __half* __restrict__ Alo_g,
               const float* __restrict__ W,
               const __half* __restrict__ Whi_g, const __half* __restrict__ Wlo_g,
               const float* __restrict__ attn,
               __half* __restrict__ C_h,
               float* __restrict__ t, int N) {
    constexpr int BM = 128, K = 128;
    constexpr int SK = K + 8;
    constexpr int WN = BN / 4;
    constexpr int MT = 2;
    constexpr int NT = WN / 8;
    constexpr int F  = BN / H;
    constexpr int THREADS = 512;

    extern __shared__ __half sm[];
    __half* sAhi = sm;
    __half* sAlo = sAhi + BM * SK;
    __half* sWhi = sAlo + BM * SK;
    __half* sWlo = sWhi + BN * SK;
    float*  sm_el = (float*)(sWlo + BN * SK);

    const int tid  = threadIdx.x;
    const int warp = tid >> 5;
    const int lane = tid & 31;
    const int row0 = blockIdx.x * BM;
    const int m0w  = (warp >> 2) * 32;
    const int n0w  = (warp & 3) * WN;
    const int fr   = lane >> 2;
    const int fc   = lane & 3;

    for (int i = tid; i < BM * H; i += THREADS) sm_el[i] = 0.f;

    if (CONV) {
        const float4* A4 = (const float4*)A;
        for (int f = tid; f < BM * 32; f += THREADS) {
            int r = f >> 5, c4 = f & 31;
            float4 v = make_float4(0.f, 0.f, 0.f, 0.f);
            if (row0 + r < N) v = A4[(size_t)(row0 + r) * 32 + c4];
            float vv[4] = {v.x, v.y, v.z, v.w};
            __half hi[4], lo[4];
#pragma unroll
            for (int j = 0; j < 4; j++) {
                hi[j] = __float2half(vv[j]);
                lo[j] = __float2half(vv[j] - __half2float(hi[j]));
            }
            int off = r * SK + c4 * 4;
            *(uint2*)&sAhi[off] = *(uint2*)hi;
            *(uint2*)&sAlo[off] = *(uint2*)lo;
        }
        const float4* W4 = (const float4*)W;
        for (int f = tid; f < BN * 32; f += THREADS) {
            int n = f >> 5, c4 = f & 31;
            float4 v = W4[(size_t)n * 32 + c4];
            float vv[4] = {v.x, v.y, v.z, v.w};
            __half hi[4], lo[4];
#pragma unroll
            for (int j = 0; j < 4; j++) {
                hi[j] = __float2half(vv[j]);
                lo[j] = __float2half(vv[j] - __half2float(hi[j]));
            }
            int off = n * SK + c4 * 4;
            *(uint2*)&sWhi[off] = *(uint2*)hi;
            *(uint2*)&sWlo[off] = *(uint2*)lo;
        }
    } else {
        const uint4* Ah = (const uint4*)Ahi_g;
        const uint4* Al = (const uint4*)Alo_g;
        for (int f = tid; f < BM * 16; f += THREADS) {
            int r = f >> 4, c8 = f & 15;
            uint4 vh = make_uint4(0u, 0u, 0u, 0u);
            uint4 vl = make_uint4(0u, 0u, 0u, 0u);
            if (row0 + r < N) {
                vh = Ah[(size_t)(row0 + r) * 16 + c8];
                vl = Al[(size_t)(row0 + r) * 16 + c8];
            }
            int off = r * SK + c8 * 8;
            *(uint4*)&sAhi[off] = vh;
            *(uint4*)&sAlo[off] = vl;
        }
        const uint4* Wh = (const uint4*)Whi_g;
        const uint4* Wl = (const uint4*)Wlo_g;
        for (int f = tid; f < BN * 16; f += THREADS) {
            int n = f >> 4, c8 = f & 15;
            int off = n * SK + c8 * 8;
            *(uint4*)&sWhi[off] = Wh[(size_t)n * 16 + c8];
            *(uint4*)&sWlo[off] = Wl[(size_t)n * 16 + c8];
        }
    }
    __syncthreads();

    float acc[MT][NT][4];
#pragma unroll
    for (int mt = 0; mt < MT; mt++)
#pragma unroll
        for (int nt = 0; nt < NT; nt++)
#pragma unroll
            for (int j = 0; j < 4; j++) acc[mt][nt][j] = 0.f;

#pragma unroll
    for (int kt = 0; kt < 8; kt++) {
        const int k0 = kt * 16;
        uint32_t ahi[MT][4], alo[MT][4];
#pragma unroll
        for (int mt = 0; mt < MT; mt++) {
            const __half* pa = &sAhi[(m0w + mt * 16 + fr) * SK + k0 + fc * 2];
            const __half* pl = &sAlo[(m0w + mt * 16 + fr) * SK + k0 + fc * 2];
            ahi[mt][0] = *(const uint32_t*)pa;
            ahi[mt][1] = *(const uint32_t*)(pa + 8 * SK);
            ahi[mt][2] = *(const uint32_t*)(pa + 8);
            ahi[mt][3] = *(const uint32_t*)(pa + 8 * SK + 8);
            alo[mt][0] = *(const uint32_t*)pl;
            alo[mt][1] = *(const uint32_t*)(pl + 8 * SK);
            alo[mt][2] = *(const uint32_t*)(pl + 8);
            alo[mt][3] = *(const uint32_t*)(pl + 8 * SK + 8);
        }
        uint32_t bhi[NT][2], blo[NT][2];
#pragma unroll
        for (int nt = 0; nt < NT; nt++) {
            const __half* pb = &sWhi[(n0w + nt * 8 + fr) * SK + k0 + fc * 2];
            const __half* pl = &sWlo[(n0w + nt * 8 + fr) * SK + k0 + fc * 2];
            bhi[nt][0] = *(const uint32_t*)pb;
            bhi[nt][1] = *(const uint32_t*)(pb + 8);
            blo[nt][0] = *(const uint32_t*)pl;
            blo[nt][1] = *(const uint32_t*)(pl + 8);
        }
#pragma unroll
        for (int mt = 0; mt < MT; mt++)
#pragma unroll
            for (int nt = 0; nt < NT; nt++) {
                mma16816(acc[mt][nt], ahi[mt], bhi[nt]);
                mma16816(acc[mt][nt], ahi[mt], blo[nt]);
                mma16816(acc[mt][nt], alo[mt], bhi[nt]);
            }
    }

    const int hh = n0w / F;
    float av0[NT], av1[NT];
#pragma unroll
    for (int nt = 0; nt < NT; nt++) {
        int col = n0w + nt * 8 + fc * 2;
        av0[nt] = attn[col];
        av1[nt] = attn[col + 1];
    }
#pragma unroll
    for (int mt = 0; mt < MT; mt++) {
        int rb0 = m0w + mt * 16 + fr;
        int rb1 = rb0 + 8;
        float p0 = 0.f, p1 = 0.f;
#pragma unroll
        for (int nt = 0; nt < NT; nt++) {
            p0 += acc[mt][nt][0] * av0[nt] + acc[mt][nt][1] * av1[nt];
            p1 += acc[mt][nt][2] * av0[nt] + acc[mt][nt][3] * av1[nt];
        }
        atomicAdd(&sm_el[rb0 * H + hh], p0);
        atomicAdd(&sm_el[rb1 * H + hh], p1);
        int g0 = row0 + rb0, g1 = row0 + rb1;
        if (g0 < N) {
#pragma unroll
            for (int nt = 0; nt < NT; nt++) {
                int col = n0w + nt * 8 + fc * 2;
                __half2 hv = __halves2half2(__float2half(acc[mt][nt][0]),
                                            __float2half(acc[mt][nt][1]));
                *(__half2*)&C_h[(size_t)g0 * BN + col] = hv;
            }
        }
        if (g1 < N) {
#pragma unroll
            for (int nt = 0; nt < NT; nt++) {
                int col = n0w + nt * 8 + fc * 2;
                __half2 hv = __halves2half2(__float2half(acc[mt][nt][2]),
                                            __float2half(acc[mt][nt][3]));
                *(__half2*)&C_h[(size_t)g1 * BN + col] = hv;
            }
        }
    }
    __syncthreads();
    for (int i = tid; i < BM * H; i += THREADS) {
        int r = i / H, h2 = i % H;
        int row = row0 + r;
        if (row < N) {
            float el = sm_el[i];
            float sv = el > 0.f ? el : 0.2f * el;
            t[(size_t)row * H + h2] = __expf(sv);
        }
    }
}

// ---------------- CSR build ----------------
__global__ void zero_cnt_kernel(int* __restrict__ cnt, int n) {
    int i = blockIdx.x * blockDim.x + threadIdx.x;
    if (i < n) cnt[i] = 0;
}

__global__ void hist_kernel(const int* __restrict__ dst, int* __restrict__ cnt, int E) {
    int i = (blockIdx.x * blockDim.x + threadIdx.x) * 4;
    if (i + 4 <= E) {
        int4 d = *(const int4*)&dst[i];
        atomicAdd(&cnt[d.x], 1);
        atomicAdd(&cnt[d.y], 1);
        atomicAdd(&cnt[d.z], 1);
        atomicAdd(&cnt[d.w], 1);
    } else {
        for (; i < E; i++) atomicAdd(&cnt[dst[i]], 1);
    }
}

__global__ void scan_kernel(const int* __restrict__ cnt, int* __restrict__ ptr,
                            int* __restrict__ cur, int N) {
    __shared__ int part[1024];
    const int tid = threadIdx.x;
    const int chunk = (N + 1023) / 1024;
    const int b = tid * chunk;
    int s = 0;
    for (int i = 0; i < chunk; i++)
        if (b + i < N) s += cnt[b + i];
    part[tid] = s;
    __syncthreads();
    for (int off = 1; off < 1024; off <<= 1) {
        int v = (tid >= off) ? part[tid - off] : 0;
        __syncthreads();
        part[tid] += v;
        __syncthreads();
    }
    int run = (tid > 0) ? part[tid - 1] : 0;
    for (int i = 0; i < chunk; i++) {
        if (b + i < N) {
            ptr[b + i] = run;
            cur[b + i] = run;
            run += cnt[b + i];
        }
    }
    if (tid == 1023) ptr[N] = part[1023];
}

__global__ void scatter_kernel(const int* __restrict__ src, const int* __restrict__ dst,
                               int* __restrict__ cur, int* __restrict__ csr, int E) {
    int i = (blockIdx.x * blockDim.x + threadIdx.x) * 4;
    if (i + 4 <= E) {
        int4 d = *(const int4*)&dst[i];
        int4 u = *(const int4*)&src[i];
        int p0 = atomicAdd(&cur[d.x], 1);
        int p1 = atomicAdd(&cur[d.y], 1);
        int p2 = atomicAdd(&cur[d.z], 1);
        int p3 = atomicAdd(&cur[d.w], 1);
        csr[p0] = u.x; csr[p1] = u.y; csr[p2] = u.z; csr[p3] = u.w;
    } else {
        for (; i < E; i++) {
            int p = atomicAdd(&cur[dst[i]], 1);
            csr[p] = src[i];
        }
    }
}

// ---------------- gather aggregation: LPN lanes per dst node ----------------
template <int H, int F, bool RELU, bool SPLITOUT>
__global__ void node_kernel(const int* __restrict__ ptr,
                            const int* __restrict__ csr,
                            const __half* __restrict__ feath,
                            const float* __restrict__ t,
                            const float* __restrict__ bias,
                            float* __restrict__ out,
                            __half* __restrict__ ohi,
                            __half* __restrict__ olo, int N) {
    constexpr int LPN = H * F / 8;            // 16 (H=2) or 8 (H=1)
    int gid  = blockIdx.x * blockDim.x + threadIdx.x;
    int node = gid / LPN;
    int lane = gid % LPN;
    if (node >= N) return;
    const int beg = ptr[node];
    const int end = ptr[node + 1];
    const int h   = (H == 2) ? (lane >> 3) : 0;

    const uint4* feat8 = (const uint4*)feath;

    float acc[8];
#pragma unroll
    for (int k = 0; k < 8; k++) acc[k] = 0.f;
    float d = 0.f;

    int i = beg;
    for (; i + 8 <= end; i += 8) {
        int u[8];
#pragma unroll
        for (int e = 0; e < 8; e++) u[e] = __ldg(&csr[i + e]);
        float tv[8];
#pragma unroll
        for (int e = 0; e < 8; e++) tv[e] = __ldg(&t[(size_t)u[e] * H + h]);
        uint4 v[8];
#pragma unroll
        for (int e = 0; e < 8; e++) v[e] = feat8[(size_t)u[e] * LPN + lane];
#pragma unroll
        for (int e = 0; e < 8; e++) {
            d += tv[e];
            const __half2* p = (const __half2*)&v[e];
#pragma unroll
            for (int k = 0; k < 4; k++) {
                float2 f = __half22float2(p[k]);
                acc[2*k]   = fmaf(tv[e], f.x, acc[2*k]);
                acc[2*k+1] = fmaf(tv[e], f.y, acc[2*k+1]);
            }
        }
    }
    for (; i + 4 <= end; i += 4) {
        int u[4];
#pragma unroll
        for (int e = 0; e < 4; e++) u[e] = __ldg(&csr[i + e]);
        float tv[4];
#pragma unroll
        for (int e = 0; e < 4; e++) tv[e] = __ldg(&t[(size_t)u[e] * H + h]);
        uint4 v[4];
#pragma unroll
        for (int e = 0; e < 4; e++) v[e] = feat8[(size_t)u[e] * LPN + lane];
#pragma unroll
        for (int e = 0; e < 4; e++) {
            d += tv[e];
            const __half2* p = (const __half2*)&v[e];
#pragma unroll
            for (int k = 0; k < 4; k++) {
                float2 f = __half22float2(p[k]);
                acc[2*k]   = fmaf(tv[e], f.x, acc[2*k]);
                acc[2*k+1] = fmaf(tv[e], f.y, acc[2*k+1]);
            }
        }
    }
    for (; i < end; i++) {
        int u = __ldg(&csr[i]);
        float tv = __ldg(&t[(size_t)u * H + h]);
        uint4 v = feat8[(size_t)u * LPN + lane];
        const __half2* p = (const __half2*)&v;
        d += tv;
#pragma unroll
        for (int k = 0; k < 4; k++) {
            float2 f = __half22float2(p[k]);
            acc[2*k]   = fmaf(tv, f.x, acc[2*k]);
            acc[2*k+1] = fmaf(tv, f.y, acc[2*k+1]);
        }
    }

    float inv = d > 0.f ? __frcp_rn(d) : 0.f;
    float vals[8];
    const float* bp = bias + lane * 8;
#pragma unroll
    for (int k = 0; k < 8; k++) {
        float v = fmaf(acc[k], inv, bp[k]);
        if (RELU) v = fmaxf(v, 0.f);
        vals[k] = v;
    }

    if (SPLITOUT) {
        __half h8[8], l8[8];
#pragma unroll
        for (int k = 0; k < 8; k++) {
            h8[k] = __float2half(vals[k]);
            l8[k] = __float2half(vals[k] - __half2float(h8[k]));
        }
        *(uint4*)&ohi[(size_t)node * (H * F) + lane * 8] = *(uint4*)h8;
        *(uint4*)&olo[(size_t)node * (H * F) + lane * 8] = *(uint4*)l8;
    } else {
        float4 o0 = make_float4(vals[0], vals[1], vals[2], vals[3]);
        float4 o1 = make_float4(vals[4], vals[5], vals[6], vals[7]);
        ((float4*)out)[(size_t)node * LPN * 2 + lane * 2 + 0] = o0;
        ((float4*)out)[(size_t)node * LPN * 2 + lane * 2 + 1] = o1;
    }
}

// ---------------------------------------------------------------------------
static cudaStream_t s_side = nullptr;
static cudaEvent_t ev_fork = nullptr, ev_csr = nullptr, ev_w = nullptr;

extern "C" void kernel_launch(void* const* d_in, const int* in_sizes, int n_in,
                              void* d_out, int out_size) {
    const float* feat    = (const float*)d_in[0];
    const float* W0      = (const float*)d_in[1];
    const float* attn_l0 = (const float*)d_in[2];
    const float* bias0   = (const float*)d_in[3];
    const float* W1      = (const float*)d_in[4];
    const float* attn_l1 = (const float*)d_in[5];
    const float* bias1   = (const float*)d_in[6];
    const float* W2      = (const float*)d_in[7];
    const float* attn_l2 = (const float*)d_in[8];
    const float* bias2   = (const float*)d_in[9];
    const int*   src     = (const int*)d_in[10];
    const int*   dst     = (const int*)d_in[11];

    const int N = in_sizes[0] / 128;
    const int E = in_sizes[10];

    __half *p_feath, *p_ahi, *p_alo, *p_w1hi, *p_w1lo, *p_w2hi, *p_w2lo;
    float *p_t;
    int *p_cnt, *p_ptr, *p_cur, *p_csr;
    cudaGetSymbolAddress((void**)&p_feath, g_feat_h);
    cudaGetSymbolAddress((void**)&p_ahi,   g_ahi);
    cudaGetSymbolAddress((void**)&p_alo,   g_alo);
    cudaGetSymbolAddress((void**)&p_w1hi,  g_w1hi);
    cudaGetSymbolAddress((void**)&p_w1lo,  g_w1lo);
    cudaGetSymbolAddress((void**)&p_w2hi,  g_w2hi);
    cudaGetSymbolAddress((void**)&p_w2lo,  g_w2lo);
    cudaGetSymbolAddress((void**)&p_t,     g_t);
    cudaGetSymbolAddress((void**)&p_cnt,   g_cnt);
    cudaGetSymbolAddress((void**)&p_ptr,   g_ptr);
    cudaGetSymbolAddress((void**)&p_cur,   g_cur);
    cudaGetSymbolAddress((void**)&p_csr,   g_csr);

    if (s_side == nullptr) {
        cudaStreamCreateWithFlags(&s_side, cudaStreamNonBlocking);
        cudaEventCreateWithFlags(&ev_fork, cudaEventDisableTiming);
        cudaEventCreateWithFlags(&ev_csr,  cudaEventDisableTiming);
        cudaEventCreateWithFlags(&ev_w,    cudaEventDisableTiming);
    }

    constexpr int SK = 128 + 8;
    const int SMEM128 = (2 * 128 + 2 * 128) * SK * 2 + 128 * 2 * 4;
    const int SMEM64  = (2 * 128 + 2 * 64)  * SK * 2 + 128 * 1 * 4;
    cudaFuncSetAttribute((const void*)gemm_tc_kernel<128, 2, true, 1>,
                         cudaFuncAttributeMaxDynamicSharedMemorySize, SMEM128);
    cudaFuncSetAttribute((const void*)gemm_tc_kernel<128, 2, false, 1>,
                         cudaFuncAttributeMaxDynamicSharedMemorySize, SMEM128);
    cudaFuncSetAttribute((const void*)gemm_tc_kernel<64, 1, false, 2>,
                         cudaFuncAttributeMaxDynamicSharedMemorySize, SMEM64);

    const int gGemm   = (N + 127) / 128;
    const int gEdge4  = (E / 4 + 255) / 256 + 1;
    const int gNode16 = (N * 16 + 255) / 256;
    const int gNode8  = (N * 8 + 255) / 256;

    // -------- fork: CSR build on side stream, GEMM0 on main --------
    cudaEventRecord(ev_fork, 0);
    cudaStreamWaitEvent(s_side, ev_fork, 0);

    zero_cnt_kernel<<<(N + 1 + 255) / 256, 256, 0, s_side>>>(p_cnt, N + 1);
    hist_kernel<<<gEdge4, 256, 0, s_side>>>(dst, p_cnt, E);
    scan_kernel<<<1, 1024, 0, s_side>>>(p_cnt, p_ptr, p_cur, N);

    gemm_tc_kernel<128, 2, true, 1><<<gGemm, 512, SMEM128>>>(
        feat, nullptr, nullptr, W0, nullptr, nullptr, attn_l0, p_feath, p_t, N);

    scatter_kernel<<<gEdge4, 256, 0, s_side>>>(src, dst, p_cur, p_csr, E);
    cudaEventRecord(ev_csr, s_side);

    // W plane precompute on side stream (hidden under gemm0/node0)
    wconv_kernel<<<(128 * 128 + 255) / 256, 256, 0, s_side>>>(W1, p_w1hi, p_w1lo, 128 * 128);
    wconv_kernel<<<(64 * 128 + 255) / 256, 256, 0, s_side>>>(W2, p_w2hi, p_w2lo, 64 * 128);
    cudaEventRecord(ev_w, s_side);

    cudaStreamWaitEvent(0, ev_csr, 0);

    // -------- layer 0 agg (MEASUREMENT: launched twice, idempotent) --------
    node_kernel<2, 64, true, true><<<gNode16, 256>>>(
        p_ptr, p_csr, p_feath, p_t, bias0, nullptr, p_ahi, p_alo, N);
    node_kernel<2, 64, true, true><<<gNode16, 256>>>(
        p_ptr, p_csr, p_feath, p_t, bias0, nullptr, p_ahi, p_alo, N);

    cudaStreamWaitEvent(0, ev_w, 0);

    // -------- layer 1 --------
    gemm_tc_kernel<128, 2, false, 1><<<gGemm, 512, SMEM128>>>(
        nullptr, p_ahi, p_alo, nullptr, p_w1hi, p_w1lo, attn_l1, p_feath, p_t, N);
    node_kernel<2, 64, true, true><<<gNode16, 256>>>(
        p_ptr, p_csr, p_feath, p_t, bias1, nullptr, p_ahi, p_alo, N);

    // -------- layer 2 (single head, no relu, write d_out) --------
    gemm_tc_kernel<64, 1, false, 2><<<gGemm, 512, SMEM64>>>(
        nullptr, p_ahi, p_alo, nullptr, p_w2hi, p_w2lo, attn_l2, p_feath, p_t, N);
    node_kernel<1, 64, false, false><<<gNode8, 256>>>(
        p_ptr, p_csr, p_feath, p_t, bias2, (float*)d_out, nullptr, nullptr, N);
}

// round 16
// speedup vs baseline: 1.0586x; 1.0586x over previous
#include <cuda_runtime.h>
#include <cuda_fp16.h>
#include <cstdint>

// ---------------------------------------------------------------------------
// GAT 3-layer forward, gather-based (CSR by dst).
// R16: gemm stages K in two 64-wide halves (single-buffered) so smem drops
// 139KB -> 75KB and TWO 512-thread blocks fit per SM (launch_bounds(512,2)).
// Same tiling/epilogue as the R14 winner; nodes/CSR/schedule unchanged.
// ---------------------------------------------------------------------------

#define MAXN 50000
#define MAXE 800000
#define MAXW 128

__device__ __half g_feat_h[MAXN * MAXW];   // gather operand (fp16 feat)
__device__ __half g_ahi[MAXN * MAXW];      // next-layer A, hi plane
__device__ __half g_alo[MAXN * MAXW];      // next-layer A, lo plane
__device__ __half g_w1hi[128 * 128], g_w1lo[128 * 128];
__device__ __half g_w2hi[64 * 128],  g_w2lo[64 * 128];
__device__ float  g_t [MAXN * 2];
__device__ int g_cnt[MAXN + 1];
__device__ int g_ptr[MAXN + 1];
__device__ int g_cur[MAXN + 1];
__device__ int g_csr[MAXE];

__device__ __forceinline__ void mma16816(float* d, const uint32_t* a, const uint32_t* b) {
    asm volatile(
        "mma.sync.aligned.m16n8k16.row.col.f32.f16.f16.f32 "
        "{%0,%1,%2,%3}, {%4,%5,%6,%7}, {%8,%9}, {%0,%1,%2,%3};\n"
        : "+f"(d[0]), "+f"(d[1]), "+f"(d[2]), "+f"(d[3])
        : "r"(a[0]), "r"(a[1]), "r"(a[2]), "r"(a[3]), "r"(b[0]), "r"(b[1]));
}

// ---------------- W hi/lo plane precompute ----------------
__global__ void wconv_kernel(const float* __restrict__ W,
                             __half* __restrict__ whi, __half* __restrict__ wlo,
                             int total) {
    int i = blockIdx.x * blockDim.x + threadIdx.x;
    if (i >= total) return;
    float v = W[i];
    __half h = __float2half(v);
    whi[i] = h;
    wlo[i] = __float2half(v - __half2float(h));
}

// ---------------- tensor-core GEMM + fused score epilogue ----------------
// BM=128, 512 threads, warp grid 4x4, warp tile 32 x WN. K staged in two
// 64-wide halves (single smem buffer, restaged) -> 2 blocks/SM.
template <int BN, int H, bool CONV>
__global__ void __launch_bounds__(512, 2)
gemm_tc_kernel(const float* __restrict__ A,
               const __half* __restrict__ Ahi_g, const __half* __restrict__ Alo_g,
               const float* __restrict__ W,
               const __half* __restrict__ Whi_g, const __half* __restrict__ Wlo_g,
               const float* __restrict__ attn,
               __half* __restrict__ C_h,
               float* __restrict__ t, int N) {
    constexpr int BM = 128;
    constexpr int HK = 64;             // K half width (halves)
    constexpr int SKH = HK + 8;        // padded stride (72)
    constexpr int WN = BN / 4;
    constexpr int MT = 2;
    constexpr int NT = WN / 8;
    constexpr int F  = BN / H;
    constexpr int THREADS = 512;

    extern __shared__ __half sm[];
    __half* sAhi = sm;                         // [BM][SKH]
    __half* sAlo = sAhi + BM * SKH;
    __half* sWhi = sAlo + BM * SKH;            // [BN][SKH]
    __half* sWlo = sWhi + BN * SKH;
    float*  sm_el = (float*)(sWlo + BN * SKH); // [BM*H]

    const int tid  = threadIdx.x;
    const int warp = tid >> 5;
    const int lane = tid & 31;
    const int row0 = blockIdx.x * BM;
    const int m0w  = (warp >> 2) * 32;
    const int n0w  = (warp & 3) * WN;
    const int fr   = lane >> 2;
    const int fc   = lane & 3;

    for (int i = tid; i < BM * H; i += THREADS) sm_el[i] = 0.f;

    float acc[MT][NT][4];
#pragma unroll
    for (int mt = 0; mt < MT; mt++)
#pragma unroll
        for (int nt = 0; nt < NT; nt++)
#pragma unroll
            for (int j = 0; j < 4; j++) acc[mt][nt][j] = 0.f;

    for (int hk = 0; hk < 2; hk++) {
        if (hk == 1) __syncthreads();   // drain reads of half 0 before restage

        // ---- stage this K-half ----
        if (CONV) {
            const float4* A4 = (const float4*)A;
            for (int f = tid; f < BM * 16; f += THREADS) {
                int r = f >> 4, c4 = f & 15;
                float4 v = make_float4(0.f, 0.f, 0.f, 0.f);
                if (row0 + r < N) v = A4[(size_t)(row0 + r) * 32 + hk * 16 + c4];
                float vv[4] = {v.x, v.y, v.z, v.w};
                __half hi[4], lo[4];
#pragma unroll
                for (int j = 0; j < 4; j++) {
                    hi[j] = __float2half(vv[j]);
                    lo[j] = __float2half(vv[j] - __half2float(hi[j]));
                }
                int off = r * SKH + c4 * 4;
                *(uint2*)&sAhi[off] = *(uint2*)hi;
                *(uint2*)&sAlo[off] = *(uint2*)lo;
            }
            const float4* W4 = (const float4*)W;
            for (int f = tid; f < BN * 16; f += THREADS) {
                int n = f >> 4, c4 = f & 15;
                float4 v = W4[(size_t)n * 32 + hk * 16 + c4];
                float vv[4] = {v.x, v.y, v.z, v.w};
                __half hi[4], lo[4];
#pragma unroll
                for (int j = 0; j < 4; j++) {
                    hi[j] = __float2half(vv[j]);
                    lo[j] = __float2half(vv[j] - __half2float(hi[j]));
                }
                int off = n * SKH + c4 * 4;
                *(uint2*)&sWhi[off] = *(uint2*)hi;
                *(uint2*)&sWlo[off] = *(uint2*)lo;
            }
        } else {
            const uint4* Ah = (const uint4*)Ahi_g;
            const uint4* Al = (const uint4*)Alo_g;
            for (int f = tid; f < BM * 8; f += THREADS) {
                int r = f >> 3, c8 = f & 7;
                uint4 vh = make_uint4(0u, 0u, 0u, 0u);
                uint4 vl = make_uint4(0u, 0u, 0u, 0u);
                if (row0 + r < N) {
                    vh = Ah[(size_t)(row0 + r) * 16 + hk * 8 + c8];
                    vl = Al[(size_t)(row0 + r) * 16 + hk * 8 + c8];
                }
                int off = r * SKH + c8 * 8;
                *(uint4*)&sAhi[off] = vh;
                *(uint4*)&sAlo[off] = vl;
            }
            const uint4* Wh = (const uint4*)Whi_g;
            const uint4* Wl = (const uint4*)Wlo_g;
            for (int f = tid; f < BN * 8; f += THREADS) {
                int n = f >> 3, c8 = f & 7;
                int off = n * SKH + c8 * 8;
                *(uint4*)&sWhi[off] = Wh[(size_t)n * 16 + hk * 8 + c8];
                *(uint4*)&sWlo[off] = Wl[(size_t)n * 16 + hk * 8 + c8];
            }
        }
        __syncthreads();

        // ---- compute this K-half ----
#pragma unroll
        for (int kt = 0; kt < 4; kt++) {
            const int k0 = kt * 16;
            uint32_t ahi[MT][4], alo[MT][4];
#pragma unroll
            for (int mt = 0; mt < MT; mt++) {
                const __half* pa = &sAhi[(m0w + mt * 16 + fr) * SKH + k0 + fc * 2];
                const __half* pl = &sAlo[(m0w + mt * 16 + fr) * SKH + k0 + fc * 2];
                ahi[mt][0] = *(const uint32_t*)pa;
                ahi[mt][1] = *(const uint32_t*)(pa + 8 * SKH);
                ahi[mt][2] = *(const uint32_t*)(pa + 8);
                ahi[mt][3] = *(const uint32_t*)(pa + 8 * SKH + 8);
                alo[mt][0] = *(const uint32_t*)pl;
                alo[mt][1] = *(const uint32_t*)(pl + 8 * SKH);
                alo[mt][2] = *(const uint32_t*)(pl + 8);
                alo[mt][3] = *(const uint32_t*)(pl + 8 * SKH + 8);
            }
            uint32_t bhi[NT][2], blo[NT][2];
#pragma unroll
            for (int nt = 0; nt < NT; nt++) {
                const __half* pb = &sWhi[(n0w + nt * 8 + fr) * SKH + k0 + fc * 2];
                const __half* pl = &sWlo[(n0w + nt * 8 + fr) * SKH + k0 + fc * 2];
                bhi[nt][0] = *(const uint32_t*)pb;
                bhi[nt][1] = *(const uint32_t*)(pb + 8);
                blo[nt][0] = *(const uint32_t*)pl;
                blo[nt][1] = *(const uint32_t*)(pl + 8);
            }
#pragma unroll
            for (int mt = 0; mt < MT; mt++)
#pragma unroll
                for (int nt = 0; nt < NT; nt++) {
                    mma16816(acc[mt][nt], ahi[mt], bhi[nt]);
                    mma16816(acc[mt][nt], ahi[mt], blo[nt]);
                    mma16816(acc[mt][nt], alo[mt], bhi[nt]);
                }
        }
    }

    // ---- epilogue: fused score partials + fp16 store ----
    const int hh = n0w / F;
    float av0[NT], av1[NT];
#pragma unroll
    for (int nt = 0; nt < NT; nt++) {
        int col = n0w + nt * 8 + fc * 2;
        av0[nt] = attn[col];
        av1[nt] = attn[col + 1];
    }
#pragma unroll
    for (int mt = 0; mt < MT; mt++) {
        int rb0 = m0w + mt * 16 + fr;
        int rb1 = rb0 + 8;
        float p0 = 0.f, p1 = 0.f;
#pragma unroll
        for (int nt = 0; nt < NT; nt++) {
            p0 += acc[mt][nt][0] * av0[nt] + acc[mt][nt][1] * av1[nt];
            p1 += acc[mt][nt][2] * av0[nt] + acc[mt][nt][3] * av1[nt];
        }
        atomicAdd(&sm_el[rb0 * H + hh], p0);
        atomicAdd(&sm_el[rb1 * H + hh], p1);
        int g0 = row0 + rb0, g1 = row0 + rb1;
        if (g0 < N) {
#pragma unroll
            for (int nt = 0; nt < NT; nt++) {
                int col = n0w + nt * 8 + fc * 2;
                __half2 hv = __halves2half2(__float2half(acc[mt][nt][0]),
                                            __float2half(acc[mt][nt][1]));
                *(__half2*)&C_h[(size_t)g0 * BN + col] = hv;
            }
        }
        if (g1 < N) {
#pragma unroll
            for (int nt = 0; nt < NT; nt++) {
                int col = n0w + nt * 8 + fc * 2;
                __half2 hv = __halves2half2(__float2half(acc[mt][nt][2]),
                                            __float2half(acc[mt][nt][3]));
                *(__half2*)&C_h[(size_t)g1 * BN + col] = hv;
            }
        }
    }
    __syncthreads();
    for (int i = tid; i < BM * H; i += THREADS) {
        int r = i / H, h2 = i % H;
        int row = row0 + r;
        if (row < N) {
            float el = sm_el[i];
            float sv = el > 0.f ? el : 0.2f * el;
            t[(size_t)row * H + h2] = __expf(sv);
        }
    }
}

// ---------------- CSR build ----------------
__global__ void zero_cnt_kernel(int* __restrict__ cnt, int n) {
    int i = blockIdx.x * blockDim.x + threadIdx.x;
    if (i < n) cnt[i] = 0;
}

__global__ void hist_kernel(const int* __restrict__ dst, int* __restrict__ cnt, int E) {
    int i = (blockIdx.x * blockDim.x + threadIdx.x) * 4;
    if (i + 4 <= E) {
        int4 d = *(const int4*)&dst[i];
        atomicAdd(&cnt[d.x], 1);
        atomicAdd(&cnt[d.y], 1);
        atomicAdd(&cnt[d.z], 1);
        atomicAdd(&cnt[d.w], 1);
    } else {
        for (; i < E; i++) atomicAdd(&cnt[dst[i]], 1);
    }
}

__global__ void scan_kernel(const int* __restrict__ cnt, int* __restrict__ ptr,
                            int* __restrict__ cur, int N) {
    __shared__ int part[1024];
    const int tid = threadIdx.x;
    const int chunk = (N + 1023) / 1024;
    const int b = tid * chunk;
    int s = 0;
    for (int i = 0; i < chunk; i++)
        if (b + i < N) s += cnt[b + i];
    part[tid] = s;
    __syncthreads();
    for (int off = 1; off < 1024; off <<= 1) {
        int v = (tid >= off) ? part[tid - off] : 0;
        __syncthreads();
        part[tid] += v;
        __syncthreads();
    }
    int run = (tid > 0) ? part[tid - 1] : 0;
    for (int i = 0; i < chunk; i++) {
        if (b + i < N) {
            ptr[b + i] = run;
            cur[b + i] = run;
            run += cnt[b + i];
        }
    }
    if (tid == 1023) ptr[N] = part[1023];
}

__global__ void scatter_kernel(const int* __restrict__ src, const int* __restrict__ dst,
                               int* __restrict__ cur, int* __restrict__ csr, int E) {
    int i = (blockIdx.x * blockDim.x + threadIdx.x) * 4;
    if (i + 4 <= E) {
        int4 d = *(const int4*)&dst[i];
        int4 u = *(const int4*)&src[i];
        int p0 = atomicAdd(&cur[d.x], 1);
        int p1 = atomicAdd(&cur[d.y], 1);
        int p2 = atomicAdd(&cur[d.z], 1);
        int p3 = atomicAdd(&cur[d.w], 1);
        csr[p0] = u.x; csr[p1] = u.y; csr[p2] = u.z; csr[p3] = u.w;
    } else {
        for (; i < E; i++) {
            int p = atomicAdd(&cur[dst[i]], 1);
            csr[p] = src[i];
        }
    }
}

// ---------------- gather aggregation: LPN lanes per dst node ----------------
template <int H, int F, bool RELU, bool SPLITOUT>
__global__ void node_kernel(const int* __restrict__ ptr,
                            const int* __restrict__ csr,
                            const __half* __restrict__ feath,
                            const float* __restrict__ t,
                            const float* __restrict__ bias,
                            float* __restrict__ out,
                            __half* __restrict__ ohi,
                            __half* __restrict__ olo, int N) {
    constexpr int LPN = H * F / 8;            // 16 (H=2) or 8 (H=1)
    int gid  = blockIdx.x * blockDim.x + threadIdx.x;
    int node = gid / LPN;
    int lane = gid % LPN;
    if (node >= N) return;
    const int beg = ptr[node];
    const int end = ptr[node + 1];
    const int h   = (H == 2) ? (lane >> 3) : 0;

    const uint4* feat8 = (const uint4*)feath;

    float acc[8];
#pragma unroll
    for (int k = 0; k < 8; k++) acc[k] = 0.f;
    float d = 0.f;

    int i = beg;
    for (; i + 8 <= end; i += 8) {
        int u[8];
#pragma unroll
        for (int e = 0; e < 8; e++) u[e] = __ldg(&csr[i + e]);
        float tv[8];
#pragma unroll
        for (int e = 0; e < 8; e++) tv[e] = __ldg(&t[(size_t)u[e] * H + h]);
        uint4 v[8];
#pragma unroll
        for (int e = 0; e < 8; e++) v[e] = feat8[(size_t)u[e] * LPN + lane];
#pragma unroll
        for (int e = 0; e < 8; e++) {
            d += tv[e];
            const __half2* p = (const __half2*)&v[e];
#pragma unroll
            for (int k = 0; k < 4; k++) {
                float2 f = __half22float2(p[k]);
                acc[2*k]   = fmaf(tv[e], f.x, acc[2*k]);
                acc[2*k+1] = fmaf(tv[e], f.y, acc[2*k+1]);
            }
        }
    }
    for (; i + 4 <= end; i += 4) {
        int u[4];
#pragma unroll
        for (int e = 0; e < 4; e++) u[e] = __ldg(&csr[i + e]);
        float tv[4];
#pragma unroll
        for (int e = 0; e < 4; e++) tv[e] = __ldg(&t[(size_t)u[e] * H + h]);
        uint4 v[4];
#pragma unroll
        for (int e = 0; e < 4; e++) v[e] = feat8[(size_t)u[e] * LPN + lane];
#pragma unroll
        for (int e = 0; e < 4; e++) {
            d += tv[e];
            const __half2* p = (const __half2*)&v[e];
#pragma unroll
            for (int k = 0; k < 4; k++) {
                float2 f = __half22float2(p[k]);
                acc[2*k]   = fmaf(tv[e], f.x, acc[2*k]);
                acc[2*k+1] = fmaf(tv[e], f.y, acc[2*k+1]);
            }
        }
    }
    for (; i < end; i++) {
        int u = __ldg(&csr[i]);
        float tv = __ldg(&t[(size_t)u * H + h]);
        uint4 v = feat8[(size_t)u * LPN + lane];
        const __half2* p = (const __half2*)&v;
        d += tv;
#pragma unroll
        for (int k = 0; k < 4; k++) {
            float2 f = __half22float2(p[k]);
            acc[2*k]   = fmaf(tv, f.x, acc[2*k]);
            acc[2*k+1] = fmaf(tv, f.y, acc[2*k+1]);
        }
    }

    float inv = d > 0.f ? __frcp_rn(d) : 0.f;
    float vals[8];
    const float* bp = bias + lane * 8;
#pragma unroll
    for (int k = 0; k < 8; k++) {
        float v = fmaf(acc[k], inv, bp[k]);
        if (RELU) v = fmaxf(v, 0.f);
        vals[k] = v;
    }

    if (SPLITOUT) {
        __half h8[8], l8[8];
#pragma unroll
        for (int k = 0; k < 8; k++) {
            h8[k] = __float2half(vals[k]);
            l8[k] = __float2half(vals[k] - __half2float(h8[k]));
        }
        *(uint4*)&ohi[(size_t)node * (H * F) + lane * 8] = *(uint4*)h8;
        *(uint4*)&olo[(size_t)node * (H * F) + lane * 8] = *(uint4*)l8;
    } else {
        float4 o0 = make_float4(vals[0], vals[1], vals[2], vals[3]);
        float4 o1 = make_float4(vals[4], vals[5], vals[6], vals[7]);
        ((float4*)out)[(size_t)node * LPN * 2 + lane * 2 + 0] = o0;
        ((float4*)out)[(size_t)node * LPN * 2 + lane * 2 + 1] = o1;
    }
}

// ---------------------------------------------------------------------------
static cudaStream_t s_side = nullptr;
static cudaEvent_t ev_fork = nullptr, ev_csr = nullptr, ev_w = nullptr;

extern "C" void kernel_launch(void* const* d_in, const int* in_sizes, int n_in,
                              void* d_out, int out_size) {
    const float* feat    = (const float*)d_in[0];
    const float* W0      = (const float*)d_in[1];
    const float* attn_l0 = (const float*)d_in[2];
    const float* bias0   = (const float*)d_in[3];
    const float* W1      = (const float*)d_in[4];
    const float* attn_l1 = (const float*)d_in[5];
    const float* bias1   = (const float*)d_in[6];
    const float* W2      = (const float*)d_in[7];
    const float* attn_l2 = (const float*)d_in[8];
    const float* bias2   = (const float*)d_in[9];
    const int*   src     = (const int*)d_in[10];
    const int*   dst     = (const int*)d_in[11];

    const int N = in_sizes[0] / 128;
    const int E = in_sizes[10];

    __half *p_feath, *p_ahi, *p_alo, *p_w1hi, *p_w1lo, *p_w2hi, *p_w2lo;
    float *p_t;
    int *p_cnt, *p_ptr, *p_cur, *p_csr;
    cudaGetSymbolAddress((void**)&p_feath, g_feat_h);
    cudaGetSymbolAddress((void**)&p_ahi,   g_ahi);
    cudaGetSymbolAddress((void**)&p_alo,   g_alo);
    cudaGetSymbolAddress((void**)&p_w1hi,  g_w1hi);
    cudaGetSymbolAddress((void**)&p_w1lo,  g_w1lo);
    cudaGetSymbolAddress((void**)&p_w2hi,  g_w2hi);
    cudaGetSymbolAddress((void**)&p_w2lo,  g_w2lo);
    cudaGetSymbolAddress((void**)&p_t,     g_t);
    cudaGetSymbolAddress((void**)&p_cnt,   g_cnt);
    cudaGetSymbolAddress((void**)&p_ptr,   g_ptr);
    cudaGetSymbolAddress((void**)&p_cur,   g_cur);
    cudaGetSymbolAddress((void**)&p_csr,   g_csr);

    if (s_side == nullptr) {
        cudaStreamCreateWithFlags(&s_side, cudaStreamNonBlocking);
        cudaEventCreateWithFlags(&ev_fork, cudaEventDisableTiming);
        cudaEventCreateWithFlags(&ev_csr,  cudaEventDisableTiming);
        cudaEventCreateWithFlags(&ev_w,    cudaEventDisableTiming);
    }

    constexpr int SKH = 64 + 8;
    const int SMEM128 = (2 * 128 + 2 * 128) * SKH * 2 + 128 * 2 * 4;  // ~74.8 KB
    const int SMEM64  = (2 * 128 + 2 * 64)  * SKH * 2 + 128 * 1 * 4;  // ~55.8 KB
    cudaFuncSetAttribute((const void*)gemm_tc_kernel<128, 2, true>,
                         cudaFuncAttributeMaxDynamicSharedMemorySize, SMEM128);
    cudaFuncSetAttribute((const void*)gemm_tc_kernel<128, 2, false>,
                         cudaFuncAttributeMaxDynamicSharedMemorySize, SMEM128);
    cudaFuncSetAttribute((const void*)gemm_tc_kernel<64, 1, false>,
                         cudaFuncAttributeMaxDynamicSharedMemorySize, SMEM64);

    const int gGemm   = (N + 127) / 128;
    const int gEdge4  = (E / 4 + 255) / 256 + 1;
    const int gNode16 = (N * 16 + 255) / 256;
    const int gNode8  = (N * 8 + 255) / 256;

    // -------- fork: CSR build on side stream, GEMM0 on main --------
    cudaEventRecord(ev_fork, 0);
    cudaStreamWaitEvent(s_side, ev_fork, 0);

    zero_cnt_kernel<<<(N + 1 + 255) / 256, 256, 0, s_side>>>(p_cnt, N + 1);
    hist_kernel<<<gEdge4, 256, 0, s_side>>>(dst, p_cnt, E);
    scan_kernel<<<1, 1024, 0, s_side>>>(p_cnt, p_ptr, p_cur, N);

    gemm_tc_kernel<128, 2, true><<<gGemm, 512, SMEM128>>>(
        feat, nullptr, nullptr, W0, nullptr, nullptr, attn_l0, p_feath, p_t, N);

    scatter_kernel<<<gEdge4, 256, 0, s_side>>>(src, dst, p_cur, p_csr, E);
    cudaEventRecord(ev_csr, s_side);

    // W plane precompute on side stream (hidden under gemm0/node0)
    wconv_kernel<<<(128 * 128 + 255) / 256, 256, 0, s_side>>>(W1, p_w1hi, p_w1lo, 128 * 128);
    wconv_kernel<<<(64 * 128 + 255) / 256, 256, 0, s_side>>>(W2, p_w2hi, p_w2lo, 64 * 128);
    cudaEventRecord(ev_w, s_side);

    cudaStreamWaitEvent(0, ev_csr, 0);

    // -------- layer 0 agg (writes A hi/lo planes) --------
    node_kernel<2, 64, true, true><<<gNode16, 256>>>(
        p_ptr, p_csr, p_feath, p_t, bias0, nullptr, p_ahi, p_alo, N);

    cudaStreamWaitEvent(0, ev_w, 0);

    // -------- layer 1 --------
    gemm_tc_kernel<128, 2, false><<<gGemm, 512, SMEM128>>>(
        nullptr, p_ahi, p_alo, nullptr, p_w1hi, p_w1lo, attn_l1, p_feath, p_t, N);
    node_kernel<2, 64, true, true><<<gNode16, 256>>>(
        p_ptr, p_csr, p_feath, p_t, bias1, nullptr, p_ahi, p_alo, N);

    // -------- layer 2 (single head, no relu, write d_out) --------
    gemm_tc_kernel<64, 1, false><<<gGemm, 512, SMEM64>>>(
        nullptr, p_ahi, p_alo, nullptr, p_w2hi, p_w2lo, attn_l2, p_feath, p_t, N);
    node_kernel<1, 64, false, false><<<gNode8, 256>>>(
        p_ptr, p_csr, p_feath, p_t, bias2, (float*)d_out, nullptr, nullptr, N);
}

// round 17
// speedup vs baseline: 1.5875x; 1.4996x over previous
#include <cuda_runtime.h>
#include <cuda_fp16.h>
#include <cstdint>

// ---------------------------------------------------------------------------
// GAT 3-layer forward, gather-based (CSR by dst).
// R17: gemm0 = half-K staging + 2 blocks/SM (measured -7us); gemm1/gemm2
// reverted to R14 full-K config. CSR scan replaced by a 3-phase coalesced
// scan so the side-stream CSR path hides under the shorter gemm0.
// ---------------------------------------------------------------------------

#define MAXN 50000
#define MAXE 800000
#define MAXW 128

__device__ __half g_feat_h[MAXN * MAXW];
__device__ __half g_ahi[MAXN * MAXW];
__device__ __half g_alo[MAXN * MAXW];
__device__ __half g_w1hi[128 * 128], g_w1lo[128 * 128];
__device__ __half g_w2hi[64 * 128],  g_w2lo[64 * 128];
__device__ float  g_t [MAXN * 2];
__device__ int g_cnt[MAXN + 1];
__device__ int g_ptr[MAXN + 1];
__device__ int g_cur[MAXN + 1];
__device__ int g_csr[MAXE];
__device__ int g_bsum[256];

__device__ __forceinline__ void mma16816(float* d, const uint32_t* a, const uint32_t* b) {
    asm volatile(
        "mma.sync.aligned.m16n8k16.row.col.f32.f16.f16.f32 "
        "{%0,%1,%2,%3}, {%4,%5,%6,%7}, {%8,%9}, {%0,%1,%2,%3};\n"
        : "+f"(d[0]), "+f"(d[1]), "+f"(d[2]), "+f"(d[3])
        : "r"(a[0]), "r"(a[1]), "r"(a[2]), "r"(a[3]), "r"(b[0]), "r"(b[1]));
}

// ---------------- W hi/lo plane precompute ----------------
__global__ void wconv_kernel(const float* __restrict__ W,
                             __half* __restrict__ whi, __half* __restrict__ wlo,
                             int total) {
    int i = blockIdx.x * blockDim.x + threadIdx.x;
    if (i >= total) return;
    float v = W[i];
    __half h = __float2half(v);
    whi[i] = h;
    wlo[i] = __float2half(v - __half2float(h));
}

// ---------------- tensor-core GEMM + fused score epilogue ----------------
// HALFK=true: K staged in two 64-wide halves (75KB smem, 2 blocks/SM).
// HALFK=false: full K staged once (R14 config, 1 block/SM).
template <int BN, int H, bool CONV, bool HALFK, int MINBLK>
__global__ void __launch_bounds__(512, MINBLK)
gemm_tc_kernel(const float* __restrict__ A,
               const __half* __restrict__ Ahi_g, const __half* __restrict__ Alo_g,
               const float* __restrict__ W,
               const __half* __restrict__ Whi_g, const __half* __restrict__ Wlo_g,
               const float* __restrict__ attn,
               __half* __restrict__ C_h,
               float* __restrict__ t, int N) {
    constexpr int BM = 128;
    constexpr int KW = HALFK ? 64 : 128;    // staged K width
    constexpr int SK = KW + 8;
    constexpr int NHALF = HALFK ? 2 : 1;
    constexpr int WN = BN / 4;
    constexpr int MT = 2;
    constexpr int NT = WN / 8;
    constexpr int F  = BN / H;
    constexpr int THREADS = 512;

    extern __shared__ __half sm[];
    __half* sAhi = sm;                         // [BM][SK]
    __half* sAlo = sAhi + BM * SK;
    __half* sWhi = sAlo + BM * SK;             // [BN][SK]
    __half* sWlo = sWhi + BN * SK;
    float*  sm_el = (float*)(sWlo + BN * SK);  // [BM*H]

    const int tid  = threadIdx.x;
    const int warp = tid >> 5;
    const int lane = tid & 31;
    const int row0 = blockIdx.x * BM;
    const int m0w  = (warp >> 2) * 32;
    const int n0w  = (warp & 3) * WN;
    const int fr   = lane >> 2;
    const int fc   = lane & 3;

    for (int i = tid; i < BM * H; i += THREADS) sm_el[i] = 0.f;

    float acc[MT][NT][4];
#pragma unroll
    for (int mt = 0; mt < MT; mt++)
#pragma unroll
        for (int nt = 0; nt < NT; nt++)
#pragma unroll
            for (int j = 0; j < 4; j++) acc[mt][nt][j] = 0.f;

    for (int hk = 0; hk < NHALF; hk++) {
        if (hk == 1) __syncthreads();

        // ---- stage this K slice ----
        if (CONV) {
            const float4* A4 = (const float4*)A;
            for (int f = tid; f < BM * (KW / 4); f += THREADS) {
                int r = f / (KW / 4), c4 = f % (KW / 4);
                float4 v = make_float4(0.f, 0.f, 0.f, 0.f);
                if (row0 + r < N)
                    v = A4[(size_t)(row0 + r) * 32 + hk * (KW / 4) + c4];
                float vv[4] = {v.x, v.y, v.z, v.w};
                __half hi[4], lo[4];
#pragma unroll
                for (int j = 0; j < 4; j++) {
                    hi[j] = __float2half(vv[j]);
                    lo[j] = __float2half(vv[j] - __half2float(hi[j]));
                }
                int off = r * SK + c4 * 4;
                *(uint2*)&sAhi[off] = *(uint2*)hi;
                *(uint2*)&sAlo[off] = *(uint2*)lo;
            }
            const float4* W4 = (const float4*)W;
            for (int f = tid; f < BN * (KW / 4); f += THREADS) {
                int n = f / (KW / 4), c4 = f % (KW / 4);
                float4 v = W4[(size_t)n * 32 + hk * (KW / 4) + c4];
                float vv[4] = {v.x, v.y, v.z, v.w};
                __half hi[4], lo[4];
#pragma unroll
                for (int j = 0; j < 4; j++) {
                    hi[j] = __float2half(vv[j]);
                    lo[j] = __float2half(vv[j] - __half2float(hi[j]));
                }
                int off = n * SK + c4 * 4;
                *(uint2*)&sWhi[off] = *(uint2*)hi;
                *(uint2*)&sWlo[off] = *(uint2*)lo;
            }
        } else {
            const uint4* Ah = (const uint4*)Ahi_g;
            const uint4* Al = (const uint4*)Alo_g;
            for (int f = tid; f < BM * (KW / 8); f += THREADS) {
                int r = f / (KW / 8), c8 = f % (KW / 8);
                uint4 vh = make_uint4(0u, 0u, 0u, 0u);
                uint4 vl = make_uint4(0u, 0u, 0u, 0u);
                if (row0 + r < N) {
                    vh = Ah[(size_t)(row0 + r) * 16 + hk * (KW / 8) + c8];
                    vl = Al[(size_t)(row0 + r) * 16 + hk * (KW / 8) + c8];
                }
                int off = r * SK + c8 * 8;
                *(uint4*)&sAhi[off] = vh;
                *(uint4*)&sAlo[off] = vl;
            }
            const uint4* Wh = (const uint4*)Whi_g;
            const uint4* Wl = (const uint4*)Wlo_g;
            for (int f = tid; f < BN * (KW / 8); f += THREADS) {
                int n = f / (KW / 8), c8 = f % (KW / 8);
                int off = n * SK + c8 * 8;
                *(uint4*)&sWhi[off] = Wh[(size_t)n * 16 + hk * (KW / 8) + c8];
                *(uint4*)&sWlo[off] = Wl[(size_t)n * 16 + hk * (KW / 8) + c8];
            }
        }
        __syncthreads();

        // ---- compute this K slice ----
#pragma unroll
        for (int kt = 0; kt < KW / 16; kt++) {
            const int k0 = kt * 16;
            uint32_t ahi[MT][4], alo[MT][4];
#pragma unroll
            for (int mt = 0; mt < MT; mt++) {
                const __half* pa = &sAhi[(m0w + mt * 16 + fr) * SK + k0 + fc * 2];
                const __half* pl = &sAlo[(m0w + mt * 16 + fr) * SK + k0 + fc * 2];
                ahi[mt][0] = *(const uint32_t*)pa;
                ahi[mt][1] = *(const uint32_t*)(pa + 8 * SK);
                ahi[mt][2] = *(const uint32_t*)(pa + 8);
                ahi[mt][3] = *(const uint32_t*)(pa + 8 * SK + 8);
                alo[mt][0] = *(const uint32_t*)pl;
                alo[mt][1] = *(const uint32_t*)(pl + 8 * SK);
                alo[mt][2] = *(const uint32_t*)(pl + 8);
                alo[mt][3] = *(const uint32_t*)(pl + 8 * SK + 8);
            }
            uint32_t bhi[NT][2], blo[NT][2];
#pragma unroll
            for (int nt = 0; nt < NT; nt++) {
                const __half* pb = &sWhi[(n0w + nt * 8 + fr) * SK + k0 + fc * 2];
                const __half* pl = &sWlo[(n0w + nt * 8 + fr) * SK + k0 + fc * 2];
                bhi[nt][0] = *(const uint32_t*)pb;
                bhi[nt][1] = *(const uint32_t*)(pb + 8);
                blo[nt][0] = *(const uint32_t*)pl;
                blo[nt][1] = *(const uint32_t*)(pl + 8);
            }
#pragma unroll
            for (int mt = 0; mt < MT; mt++)
#pragma unroll
                for (int nt = 0; nt < NT; nt++) {
                    mma16816(acc[mt][nt], ahi[mt], bhi[nt]);
                    mma16816(acc[mt][nt], ahi[mt], blo[nt]);
                    mma16816(acc[mt][nt], alo[mt], bhi[nt]);
                }
        }
    }

    // ---- epilogue: fused score partials + fp16 store ----
    const int hh = n0w / F;
    float av0[NT], av1[NT];
#pragma unroll
    for (int nt = 0; nt < NT; nt++) {
        int col = n0w + nt * 8 + fc * 2;
        av0[nt] = attn[col];
        av1[nt] = attn[col + 1];
    }
#pragma unroll
    for (int mt = 0; mt < MT; mt++) {
        int rb0 = m0w + mt * 16 + fr;
        int rb1 = rb0 + 8;
        float p0 = 0.f, p1 = 0.f;
#pragma unroll
        for (int nt = 0; nt < NT; nt++) {
            p0 += acc[mt][nt][0] * av0[nt] + acc[mt][nt][1] * av1[nt];
            p1 += acc[mt][nt][2] * av0[nt] + acc[mt][nt][3] * av1[nt];
        }
        atomicAdd(&sm_el[rb0 * H + hh], p0);
        atomicAdd(&sm_el[rb1 * H + hh], p1);
        int g0 = row0 + rb0, g1 = row0 + rb1;
        if (g0 < N) {
#pragma unroll
            for (int nt = 0; nt < NT; nt++) {
                int col = n0w + nt * 8 + fc * 2;
                __half2 hv = __halves2half2(__float2half(acc[mt][nt][0]),
                                            __float2half(acc[mt][nt][1]));
                *(__half2*)&C_h[(size_t)g0 * BN + col] = hv;
            }
        }
        if (g1 < N) {
#pragma unroll
            for (int nt = 0; nt < NT; nt++) {
                int col = n0w + nt * 8 + fc * 2;
                __half2 hv = __halves2half2(__float2half(acc[mt][nt][2]),
                                            __float2half(acc[mt][nt][3]));
                *(__half2*)&C_h[(size_t)g1 * BN + col] = hv;
            }
        }
    }
    __syncthreads();
    for (int i = tid; i < BM * H; i += THREADS) {
        int r = i / H, h2 = i % H;
        int row = row0 + r;
        if (row < N) {
            float el = sm_el[i];
            float sv = el > 0.f ? el : 0.2f * el;
            t[(size_t)row * H + h2] = __expf(sv);
        }
    }
}

// ---------------- CSR build ----------------
__global__ void zero_cnt_kernel(int* __restrict__ cnt, int n) {
    int i = blockIdx.x * blockDim.x + threadIdx.x;
    if (i < n) cnt[i] = 0;
}

__global__ void hist_kernel(const int* __restrict__ dst, int* __restrict__ cnt, int E) {
    int i = (blockIdx.x * blockDim.x + threadIdx.x) * 4;
    if (i + 4 <= E) {
        int4 d = *(const int4*)&dst[i];
        atomicAdd(&cnt[d.x], 1);
        atomicAdd(&cnt[d.y], 1);
        atomicAdd(&cnt[d.z], 1);
        atomicAdd(&cnt[d.w], 1);
    } else {
        for (; i < E; i++) atomicAdd(&cnt[dst[i]], 1);
    }
}

// 3-phase coalesced scan over cnt[0..N) -> ptr/cur (exclusive), ptr[N]=total
__global__ void scan1_kernel(const int* __restrict__ cnt, int* __restrict__ bsum, int N) {
    __shared__ int s[256];
    int i = blockIdx.x * 256 + threadIdx.x;
    s[threadIdx.x] = (i < N) ? cnt[i] : 0;
    __syncthreads();
    for (int off = 128; off > 0; off >>= 1) {
        if (threadIdx.x < off) s[threadIdx.x] += s[threadIdx.x + off];
        __syncthreads();
    }
    if (threadIdx.x == 0) bsum[blockIdx.x] = s[0];
}

__global__ void scan2_kernel(int* __restrict__ bsum, int nb) {
    __shared__ int s[256];
    int t = threadIdx.x;
    int v = (t < nb) ? bsum[t] : 0;
    s[t] = v;
    __syncthreads();
    for (int off = 1; off < 256; off <<= 1) {
        int x = (t >= off) ? s[t - off] : 0;
        __syncthreads();
        s[t] += x;
        __syncthreads();
    }
    if (t < nb) bsum[t] = s[t] - v;   // exclusive
}

__global__ void scan3_kernel(const int* __restrict__ cnt, const int* __restrict__ bsum,
                             int* __restrict__ ptr, int* __restrict__ cur, int N) {
    __shared__ int s[256];
    int t = threadIdx.x;
    int i = blockIdx.x * 256 + t;
    int v = (i < N) ? cnt[i] : 0;
    s[t] = v;
    __syncthreads();
    for (int off = 1; off < 256; off <<= 1) {
        int x = (t >= off) ? s[t - off] : 0;
        __syncthreads();
        s[t] += x;
        __syncthreads();
    }
    int excl = s[t] - v + bsum[blockIdx.x];
    if (i < N) {
        ptr[i] = excl;
        cur[i] = excl;
        if (i == N - 1) ptr[N] = excl + v;
    }
}

__global__ void scatter_kernel(const int* __restrict__ src, const int* __restrict__ dst,
                               int* __restrict__ cur, int* __restrict__ csr, int E) {
    int i = (blockIdx.x * blockDim.x + threadIdx.x) * 4;
    if (i + 4 <= E) {
        int4 d = *(const int4*)&dst[i];
        int4 u = *(const int4*)&src[i];
        int p0 = atomicAdd(&cur[d.x], 1);
        int p1 = atomicAdd(&cur[d.y], 1);
        int p2 = atomicAdd(&cur[d.z], 1);
        int p3 = atomicAdd(&cur[d.w], 1);
        csr[p0] = u.x; csr[p1] = u.y; csr[p2] = u.z; csr[p3] = u.w;
    } else {
        for (; i < E; i++) {
            int p = atomicAdd(&cur[dst[i]], 1);
            csr[p] = src[i];
        }
    }
}

// ---------------- gather aggregation: LPN lanes per dst node ----------------
template <int H, int F, bool RELU, bool SPLITOUT>
__global__ void node_kernel(const int* __restrict__ ptr,
                            const int* __restrict__ csr,
                            const __half* __restrict__ feath,
                            const float* __restrict__ t,
                            const float* __restrict__ bias,
                            float* __restrict__ out,
                            __half* __restrict__ ohi,
                            __half* __restrict__ olo, int N) {
    constexpr int LPN = H * F / 8;
    int gid  = blockIdx.x * blockDim.x + threadIdx.x;
    int node = gid / LPN;
    int lane = gid % LPN;
    if (node >= N) return;
    const int beg = ptr[node];
    const int end = ptr[node + 1];
    const int h   = (H == 2) ? (lane >> 3) : 0;

    const uint4* feat8 = (const uint4*)feath;

    float acc[8];
#pragma unroll
    for (int k = 0; k < 8; k++) acc[k] = 0.f;
    float d = 0.f;

    int i = beg;
    for (; i + 8 <= end; i += 8) {
        int u[8];
#pragma unroll
        for (int e = 0; e < 8; e++) u[e] = __ldg(&csr[i + e]);
        float tv[8];
#pragma unroll
        for (int e = 0; e < 8; e++) tv[e] = __ldg(&t[(size_t)u[e] * H + h]);
        uint4 v[8];
#pragma unroll
        for (int e = 0; e < 8; e++) v[e] = feat8[(size_t)u[e] * LPN + lane];
#pragma unroll
        for (int e = 0; e < 8; e++) {
            d += tv[e];
            const __half2* p = (const __half2*)&v[e];
#pragma unroll
            for (int k = 0; k < 4; k++) {
                float2 f = __half22float2(p[k]);
                acc[2*k]   = fmaf(tv[e], f.x, acc[2*k]);
                acc[2*k+1] = fmaf(tv[e], f.y, acc[2*k+1]);
            }
        }
    }
    for (; i + 4 <= end; i += 4) {
        int u[4];
#pragma unroll
        for (int e = 0; e < 4; e++) u[e] = __ldg(&csr[i + e]);
        float tv[4];
#pragma unroll
        for (int e = 0; e < 4; e++) tv[e] = __ldg(&t[(size_t)u[e] * H + h]);
        uint4 v[4];
#pragma unroll
        for (int e = 0; e < 4; e++) v[e] = feat8[(size_t)u[e] * LPN + lane];
#pragma unroll
        for (int e = 0; e < 4; e++) {
            d += tv[e];
            const __half2* p = (const __half2*)&v[e];
#pragma unroll
            for (int k = 0; k < 4; k++) {
                float2 f = __half22float2(p[k]);
                acc[2*k]   = fmaf(tv[e], f.x, acc[2*k]);
                acc[2*k+1] = fmaf(tv[e], f.y, acc[2*k+1]);
            }
        }
    }
    for (; i < end; i++) {
        int u = __ldg(&csr[i]);
        float tv = __ldg(&t[(size_t)u * H + h]);
        uint4 v = feat8[(size_t)u * LPN + lane];
        const __half2* p = (const __half2*)&v;
        d += tv;
#pragma unroll
        for (int k = 0; k < 4; k++) {
            float2 f = __half22float2(p[k]);
            acc[2*k]   = fmaf(tv, f.x, acc[2*k]);
            acc[2*k+1] = fmaf(tv, f.y, acc[2*k+1]);
        }
    }

    float inv = d > 0.f ? __frcp_rn(d) : 0.f;
    float vals[8];
    const float* bp = bias + lane * 8;
#pragma unroll
    for (int k = 0; k < 8; k++) {
        float v = fmaf(acc[k], inv, bp[k]);
        if (RELU) v = fmaxf(v, 0.f);
        vals[k] = v;
    }

    if (SPLITOUT) {
        __half h8[8], l8[8];
#pragma unroll
        for (int k = 0; k < 8; k++) {
            h8[k] = __float2half(vals[k]);
            l8[k] = __float2half(vals[k] - __half2float(h8[k]));
        }
        *(uint4*)&ohi[(size_t)node * (H * F) + lane * 8] = *(uint4*)h8;
        *(uint4*)&olo[(size_t)node * (H * F) + lane * 8] = *(uint4*)l8;
    } else {
        float4 o0 = make_float4(vals[0], vals[1], vals[2], vals[3]);
        float4 o1 = make_float4(vals[4], vals[5], vals[6], vals[7]);
        ((float4*)out)[(size_t)node * LPN * 2 + lane * 2 + 0] = o0;
        ((float4*)out)[(size_t)node * LPN * 2 + lane * 2 + 1] = o1;
    }
}

// ---------------------------------------------------------------------------
static cudaStream_t s_side = nullptr;
static cudaEvent_t ev_fork = nullptr, ev_csr = nullptr, ev_w = nullptr;

extern "C" void kernel_launch(void* const* d_in, const int* in_sizes, int n_in,
                              void* d_out, int out_size) {
    const float* feat    = (const float*)d_in[0];
    const float* W0      = (const float*)d_in[1];
    const float* attn_l0 = (const float*)d_in[2];
    const float* bias0   = (const float*)d_in[3];
    const float* W1      = (const float*)d_in[4];
    const float* attn_l1 = (const float*)d_in[5];
    const float* bias1   = (const float*)d_in[6];
    const float* W2      = (const float*)d_in[7];
    const float* attn_l2 = (const float*)d_in[8];
    const float* bias2   = (const float*)d_in[9];
    const int*   src     = (const int*)d_in[10];
    const int*   dst     = (const int*)d_in[11];

    const int N = in_sizes[0] / 128;
    const int E = in_sizes[10];

    __half *p_feath, *p_ahi, *p_alo, *p_w1hi, *p_w1lo, *p_w2hi, *p_w2lo;
    float *p_t;
    int *p_cnt, *p_ptr, *p_cur, *p_csr, *p_bsum;
    cudaGetSymbolAddress((void**)&p_feath, g_feat_h);
    cudaGetSymbolAddress((void**)&p_ahi,   g_ahi);
    cudaGetSymbolAddress((void**)&p_alo,   g_alo);
    cudaGetSymbolAddress((void**)&p_w1hi,  g_w1hi);
    cudaGetSymbolAddress((void**)&p_w1lo,  g_w1lo);
    cudaGetSymbolAddress((void**)&p_w2hi,  g_w2hi);
    cudaGetSymbolAddress((void**)&p_w2lo,  g_w2lo);
    cudaGetSymbolAddress((void**)&p_t,     g_t);
    cudaGetSymbolAddress((void**)&p_cnt,   g_cnt);
    cudaGetSymbolAddress((void**)&p_ptr,   g_ptr);
    cudaGetSymbolAddress((void**)&p_cur,   g_cur);
    cudaGetSymbolAddress((void**)&p_csr,   g_csr);
    cudaGetSymbolAddress((void**)&p_bsum,  g_bsum);

    if (s_side == nullptr) {
        cudaStreamCreateWithFlags(&s_side, cudaStreamNonBlocking);
        cudaEventCreateWithFlags(&ev_fork, cudaEventDisableTiming);
        cudaEventCreateWithFlags(&ev_csr,  cudaEventDisableTiming);
        cudaEventCreateWithFlags(&ev_w,    cudaEventDisableTiming);
    }

    // smem sizes: gemm0 half-K (SK=72), gemm1/2 full-K (SK=136)
    const int SMEM0 = (2 * 128 + 2 * 128) * 72  * 2 + 128 * 2 * 4;   // ~74.8 KB
    const int SMEM1 = (2 * 128 + 2 * 128) * 136 * 2 + 128 * 2 * 4;   // ~137 KB
    const int SMEM2 = (2 * 128 + 2 * 64)  * 136 * 2 + 128 * 1 * 4;   // ~102.5 KB
    cudaFuncSetAttribute((const void*)gemm_tc_kernel<128, 2, true,  true,  2>,
                         cudaFuncAttributeMaxDynamicSharedMemorySize, SMEM0);
    cudaFuncSetAttribute((const void*)gemm_tc_kernel<128, 2, false, false, 1>,
                         cudaFuncAttributeMaxDynamicSharedMemorySize, SMEM1);
    cudaFuncSetAttribute((const void*)gemm_tc_kernel<64, 1, false, false, 1>,
                         cudaFuncAttributeMaxDynamicSharedMemorySize, SMEM2);

    const int gGemm   = (N + 127) / 128;
    const int gEdge4  = (E / 4 + 255) / 256 + 1;
    const int gScan   = (N + 255) / 256;
    const int gNode16 = (N * 16 + 255) / 256;
    const int gNode8  = (N * 8 + 255) / 256;

    // -------- fork: CSR build on side stream, GEMM0 on main --------
    cudaEventRecord(ev_fork, 0);
    cudaStreamWaitEvent(s_side, ev_fork, 0);

    zero_cnt_kernel<<<(N + 1 + 255) / 256, 256, 0, s_side>>>(p_cnt, N + 1);
    hist_kernel<<<gEdge4, 256, 0, s_side>>>(dst, p_cnt, E);
    scan1_kernel<<<gScan, 256, 0, s_side>>>(p_cnt, p_bsum, N);

    // gemm0 kept as 4th submission (profiler slot continuity)
    gemm_tc_kernel<128, 2, true, true, 2><<<gGemm, 512, SMEM0>>>(
        feat, nullptr, nullptr, W0, nullptr, nullptr, attn_l0, p_feath, p_t, N);

    scan2_kernel<<<1, 256, 0, s_side>>>(p_bsum, gScan);
    scan3_kernel<<<gScan, 256, 0, s_side>>>(p_cnt, p_bsum, p_ptr, p_cur, N);
    scatter_kernel<<<gEdge4, 256, 0, s_side>>>(src, dst, p_cur, p_csr, E);
    cudaEventRecord(ev_csr, s_side);

    wconv_kernel<<<(128 * 128 + 255) / 256, 256, 0, s_side>>>(W1, p_w1hi, p_w1lo, 128 * 128);
    wconv_kernel<<<(64 * 128 + 255) / 256, 256, 0, s_side>>>(W2, p_w2hi, p_w2lo, 64 * 128);
    cudaEventRecord(ev_w, s_side);

    cudaStreamWaitEvent(0, ev_csr, 0);

    // -------- layer 0 agg (writes A hi/lo planes) --------
    node_kernel<2, 64, true, true><<<gNode16, 256>>>(
        p_ptr, p_csr, p_feath, p_t, bias0, nullptr, p_ahi, p_alo, N);

    cudaStreamWaitEvent(0, ev_w, 0);

    // -------- layer 1 --------
    gemm_tc_kernel<128, 2, false, false, 1><<<gGemm, 512, SMEM1>>>(
        nullptr, p_ahi, p_alo, nullptr, p_w1hi, p_w1lo, attn_l1, p_feath, p_t, N);
    node_kernel<2, 64, true, true><<<gNode16, 256>>>(
        p_ptr, p_csr, p_feath, p_t, bias1, nullptr, p_ahi, p_alo, N);

    // -------- layer 2 (single head, no relu, write d_out) --------
    gemm_tc_kernel<64, 1, false, false, 1><<<gGemm, 512, SMEM2>>>(
        nullptr, p_ahi, p_alo, nullptr, p_w2hi, p_w2lo, attn_l2, p_feath, p_t, N);
    node_kernel<1, 64, false, false><<<gNode8, 256>>>(
        p_ptr, p_csr, p_feath, p_t, bias2, (float*)d_out, nullptr, nullptr, N);
}